// round 7
// baseline (speedup 1.0000x reference)
#include <cuda_runtime.h>

#define BB 8
#define LL 512
#define DD 128

typedef unsigned long long ull;

// Scratch (allocation-free rule: __device__ globals)
__device__ float g_eq[BB * DD * LL];  // [b][d][l]  e^{2q}, l contiguous
__device__ float g_ek[BB * LL * DD];  // [b][l][d]  e^{2k}

// ---- packed f32x2 helpers (sm_100a) ----
__device__ __forceinline__ ull fma2(ull a, ull b, ull c) {
    ull d; asm("fma.rn.f32x2 %0, %1, %2, %3;" : "=l"(d) : "l"(a), "l"(b), "l"(c)); return d;
}
__device__ __forceinline__ ull mul2(ull a, ull b) {
    ull d; asm("mul.rn.f32x2 %0, %1, %2;" : "=l"(d) : "l"(a), "l"(b)); return d;
}
__device__ __forceinline__ void unpack_u32(ull v, unsigned& lo, unsigned& hi) {
    asm("mov.b64 {%0, %1}, %2;" : "=r"(lo), "=r"(hi) : "l"(v));
}
__device__ __forceinline__ ull pack_u32(unsigned lo, unsigned hi) {
    ull v; asm("mov.b64 %0, {%1, %2};" : "=l"(v) : "r"(lo), "r"(hi)); return v;
}
__device__ __forceinline__ void unpack_f32(ull v, float& lo, float& hi) {
    asm("mov.b64 {%0, %1}, %2;" : "=f"(lo), "=f"(hi) : "l"(v));
}
__device__ __forceinline__ ull pack_f32(float lo, float hi) {
    ull v; asm("mov.b64 %0, {%1, %2};" : "=l"(v) : "f"(lo), "f"(hi)); return v;
}
__device__ __forceinline__ float rcp_fast(float x) {
    float y; asm("rcp.approx.f32 %0, %1;" : "=f"(y) : "f"(x)); return y;
}

#define ONE2 0x3F8000003F800000ULL
#define TWO2 0x4000000040000000ULL

// ---------------------------------------------------------------------------
// Kernel A: Eq = exp(2 * inp@u_w^T) stored transposed [b][d][l],
//           Ek = exp(2 * inp@v_w^T) row-major [b][l][d]
// ---------------------------------------------------------------------------
__global__ __launch_bounds__(256, 2) void proj_kernel(
    const float* __restrict__ inp,
    const float* __restrict__ uw,
    const float* __restrict__ vw)
{
    __shared__ float xS[32][32];
    __shared__ float wuS[128][33];
    __shared__ float wvS[128][33];

    const int b    = blockIdx.x >> 4;
    const int l0   = (blockIdx.x & 15) << 5;
    const int t    = threadIdx.x;
    const int lane = t & 31;
    const int warp = t >> 5;
    const int lrow = warp << 2;

    float qacc[4][4], kacc[4][4];
#pragma unroll
    for (int i = 0; i < 4; i++)
#pragma unroll
        for (int jj = 0; jj < 4; jj++) { qacc[i][jj] = 0.f; kacc[i][jj] = 0.f; }

    for (int kc = 0; kc < 4; kc++) {
        const int d0 = kc << 5;
        for (int idx = t; idx < 32 * 32; idx += 256) {
            int r = idx >> 5, c = idx & 31;
            xS[r][c] = inp[(b * LL + l0 + r) * DD + d0 + c];
        }
        for (int idx = t; idx < 128 * 32; idx += 256) {
            int r = idx >> 5, c = idx & 31;
            wuS[r][c] = uw[r * DD + d0 + c];
            wvS[r][c] = vw[r * DD + d0 + c];
        }
        __syncthreads();

#pragma unroll 8
        for (int d = 0; d < 32; d++) {
            const float x0 = xS[lrow + 0][d];
            const float x1 = xS[lrow + 1][d];
            const float x2 = xS[lrow + 2][d];
            const float x3 = xS[lrow + 3][d];
#pragma unroll
            for (int jj = 0; jj < 4; jj++) {
                const int e = lane + (jj << 5);
                const float wu = wuS[e][d];
                const float wv = wvS[e][d];
                qacc[0][jj] = fmaf(x0, wu, qacc[0][jj]);
                qacc[1][jj] = fmaf(x1, wu, qacc[1][jj]);
                qacc[2][jj] = fmaf(x2, wu, qacc[2][jj]);
                qacc[3][jj] = fmaf(x3, wu, qacc[3][jj]);
                kacc[0][jj] = fmaf(x0, wv, kacc[0][jj]);
                kacc[1][jj] = fmaf(x1, wv, kacc[1][jj]);
                kacc[2][jj] = fmaf(x2, wv, kacc[2][jj]);
                kacc[3][jj] = fmaf(x3, wv, kacc[3][jj]);
            }
        }
        __syncthreads();
    }

#pragma unroll
    for (int jj = 0; jj < 4; jj++) {
        const int e = lane + (jj << 5);
#pragma unroll
        for (int i = 0; i < 4; i++) {
            const int l = l0 + lrow + i;
            g_eq[((size_t)b * DD + e) * LL + l] = __expf(2.0f * qacc[i][jj]);
            g_ek[((size_t)b * LL + l) * DD + e] = __expf(2.0f * kacc[i][jj]);
        }
    }
}

// ---------------------------------------------------------------------------
// Kernel B: fused score + softmax + attn-write + out GEMM.
// score_ij ∝ -2 * sum_d a_d / (Eq[j,d]*Ek[i,d] + 1)   (constant dropped)
// Even d -> MUFU rcp path; odd d -> FMA magic-Newton path (pipes overlap).
// grid = 512 blocks, 512 threads (16 warps): d-half (2) x j-tile-of-64 (8).
// Lane packs 2 adjacent j's in an f32x2.
// smem: outS overlaid on kS2/aS2 (disjoint lifetimes) to stay under 48KB.
// ---------------------------------------------------------------------------
__global__ __launch_bounds__(512, 2) void attn_kernel(
    const float* __restrict__ inp,
    const float* __restrict__ aw,
    float* __restrict__ out,
    float* __restrict__ attn)
{
    union SmemOverlay {
        struct {
            ull kS2[8][128];   // Ek duplicated into both f32x2 lanes (phase 2)
            ull aS2[128];      // +/-a_d duplicated (phase 2)
        } p2;
        float outS[2][8][128]; // phase 4 partial outputs
    };
    __shared__ __align__(16) SmemOverlay ov;
    __shared__ float scp[2][8][512];            // per-d-half partial (-sum a_d r_d)

    const int b    = blockIdx.x >> 6;
    const int i0   = (blockIdx.x & 63) << 3;
    const int t    = threadIdx.x;
    const int lane = t & 31;
    const int w    = t >> 5;

    // Stage Ek (duplicated) and signed a (duplicated)
    for (int idx = t; idx < 8 * 128; idx += 512) {
        const int ii = idx >> 7, d = idx & 127;
        const float kv = g_ek[((size_t)b * LL + i0 + ii) * DD + d];
        unsigned kb = __float_as_uint(kv);
        ov.p2.kS2[ii][d] = pack_u32(kb, kb);
    }
    if (t < 128) {
        const float av = aw[t];
        const float sv = (t & 1) ? av : -av;   // even d = rcp path -> store -a
        unsigned ab = __float_as_uint(sv);
        ov.p2.aS2[t] = pack_u32(ab, ab);
    }
    __syncthreads();

    // ---- Phase 2 ----
    const int h     = w >> 3;            // d-half
    const int jb    = (w & 7) << 6;      // 64-j tile
    const int dbase = h << 6;

    ull acc2[8];
#pragma unroll
    for (int ii = 0; ii < 8; ii++) acc2[ii] = 0ULL;

    const float* __restrict__ eqBase = g_eq + (size_t)b * DD * LL + jb + (lane << 1);

#pragma unroll 4
    for (int d2 = 0; d2 < 32; d2++) {
        const int dE = dbase + (d2 << 1);      // even -> rcp (MUFU)
        const int dO = dE + 1;                 // odd  -> magic-Newton (FMA)
        const ull Eq2E = *(const ull*)(eqBase + (size_t)dE * LL);   // coalesced LDG.64
        const ull Eq2O = *(const ull*)(eqBase + (size_t)dO * LL);
        const ull a2E = ov.p2.aS2[dE];   // holds (-a,-a)
        const ull a2O = ov.p2.aS2[dO];   // holds (+a,+a)
#pragma unroll
        for (int ii = 0; ii < 8; ii++) {
            // MUFU path: r = 1/(Eq*Ek+1), acc += (-a)*r
            {
                const ull x2 = fma2(Eq2E, ov.p2.kS2[ii][dE], ONE2);
                float xl, xh; unpack_f32(x2, xl, xh);
                const float rl = rcp_fast(xl);
                const float rh = rcp_fast(xh);
                acc2[ii] = fma2(a2E, pack_f32(rl, rh), acc2[ii]);
            }
            // FMA path: negated magic seed + 2 Newton iters, acc += a*(-r)
            {
                const ull x2 = fma2(Eq2O, ov.p2.kS2[ii][dO], ONE2);
                unsigned il, ih; unpack_u32(x2, il, ih);
                const ull nr0 = pack_u32(0xFEF311C3u - il, 0xFEF311C3u - ih); // = -r0
                const ull t1  = fma2(x2, nr0, TWO2);    // 2 - x*r0
                const ull nr1 = mul2(nr0, t1);          // -r1
                const ull t2  = fma2(x2, nr1, TWO2);    // 2 - x*r1
                const ull nr2 = mul2(nr1, t2);          // -r2
                acc2[ii] = fma2(a2O, nr2, acc2[ii]);
            }
        }
    }
    {
        const int j = jb + (lane << 1);
#pragma unroll
        for (int ii = 0; ii < 8; ii++) {
            float alo, ahi; unpack_f32(acc2[ii], alo, ahi);
            scp[h][ii][j]     = alo;
            scp[h][ii][j + 1] = ahi;
        }
    }
    __syncthreads();   // kS2/aS2 dead beyond this point

    // ---- Phase 3: softmax over j (score = 2*(acc_h0+acc_h1) + const) ----
    if (w < 8) {
        const int r = w;
        float v[16];
        float mx = -1e30f;
#pragma unroll
        for (int q = 0; q < 16; q++) {
            const int jj = lane + (q << 5);
            v[q] = 2.0f * (scp[0][r][jj] + scp[1][r][jj]);
            mx = fmaxf(mx, v[q]);
        }
#pragma unroll
        for (int o = 16; o > 0; o >>= 1) mx = fmaxf(mx, __shfl_xor_sync(0xffffffffu, mx, o));
        float s = 0.f;
#pragma unroll
        for (int q = 0; q < 16; q++) { v[q] = __expf(v[q] - mx); s += v[q]; }
#pragma unroll
        for (int o = 16; o > 0; o >>= 1) s += __shfl_xor_sync(0xffffffffu, s, o);
        const float inv = 1.0f / s;
        float* arow = attn + ((size_t)b * LL + i0 + r) * LL;
#pragma unroll
        for (int q = 0; q < 16; q++) {
            const int jj = lane + (q << 5);
            const float av = v[q] * inv;
            scp[0][r][jj] = av;   // reuse for GEMM
            arow[jj]      = av;   // coalesced attn output
        }
    }
    __syncthreads();

    // ---- Phase 4: out[i,:] = sum_j attn[i,j] * inp[b,j,:] ----
    {
        const int r = w & 7, hh = w >> 3;
        float4 racc = make_float4(0.f, 0.f, 0.f, 0.f);
        const float4* __restrict__ xin =
            (const float4*)(inp + (size_t)(b * LL + (hh << 8)) * DD) + lane;
#pragma unroll 8
        for (int jj = 0; jj < 256; jj++) {
            const float av = scp[0][r][(hh << 8) + jj];   // broadcast
            const float4 xv = xin[jj * (DD / 4)];         // coalesced LDG.128
            racc.x = fmaf(av, xv.x, racc.x);
            racc.y = fmaf(av, xv.y, racc.y);
            racc.z = fmaf(av, xv.z, racc.z);
            racc.w = fmaf(av, xv.w, racc.w);
        }
        *(float4*)&ov.outS[hh][r][lane << 2] = racc;
    }
    __syncthreads();
    if (w < 8) {
        const int r = w;
        const float4 o0 = *(const float4*)&ov.outS[0][r][lane << 2];
        const float4 o1 = *(const float4*)&ov.outS[1][r][lane << 2];
        float4 o = make_float4(o0.x + o1.x, o0.y + o1.y, o0.z + o1.z, o0.w + o1.w);
        *(float4*)&out[((size_t)b * LL + i0 + r) * DD + (lane << 2)] = o;
    }
}

// ---------------------------------------------------------------------------
extern "C" void kernel_launch(void* const* d_in, const int* in_sizes, int n_in,
                              void* d_out, int out_size)
{
    const float* inp = (const float*)d_in[0];
    const float* uw  = (const float*)d_in[1];
    const float* vw  = (const float*)d_in[2];
    const float* aw  = (const float*)d_in[3];

    float* out  = (float*)d_out;
    float* attn = out + BB * LL * DD;

    proj_kernel<<<BB * (LL / 32), 256>>>(inp, uw, vw);
    attn_kernel<<<BB * (LL / 8), 512>>>(inp, aw, out, attn);
}

// round 8
// speedup vs baseline: 1.0262x; 1.0262x over previous
#include <cuda_runtime.h>

#define BB 8
#define LL 512
#define DD 128

// Scratch (allocation-free rule: __device__ globals)
__device__ float g_eq[BB * DD * LL];  // [b][d][l]  e^{2q}, l contiguous
__device__ float g_ek[BB * LL * DD];  // [b][l][d]  e^{2k}

__device__ __forceinline__ float rcp_fast(float x) {
    float y; asm("rcp.approx.f32 %0, %1;" : "=f"(y) : "f"(x)); return y;
}

// ---------------------------------------------------------------------------
// Kernel A: Eq = exp(2 * inp@u_w^T) stored transposed [b][d][l],
//           Ek = exp(2 * inp@v_w^T) row-major [b][l][d]
// ---------------------------------------------------------------------------
__global__ __launch_bounds__(256, 2) void proj_kernel(
    const float* __restrict__ inp,
    const float* __restrict__ uw,
    const float* __restrict__ vw)
{
    __shared__ float xS[32][32];
    __shared__ float wuS[128][33];
    __shared__ float wvS[128][33];

    const int b    = blockIdx.x >> 4;
    const int l0   = (blockIdx.x & 15) << 5;
    const int t    = threadIdx.x;
    const int lane = t & 31;
    const int warp = t >> 5;
    const int lrow = warp << 2;

    float qacc[4][4], kacc[4][4];
#pragma unroll
    for (int i = 0; i < 4; i++)
#pragma unroll
        for (int jj = 0; jj < 4; jj++) { qacc[i][jj] = 0.f; kacc[i][jj] = 0.f; }

    for (int kc = 0; kc < 4; kc++) {
        const int d0 = kc << 5;
        for (int idx = t; idx < 32 * 32; idx += 256) {
            int r = idx >> 5, c = idx & 31;
            xS[r][c] = inp[(b * LL + l0 + r) * DD + d0 + c];
        }
        for (int idx = t; idx < 128 * 32; idx += 256) {
            int r = idx >> 5, c = idx & 31;
            wuS[r][c] = uw[r * DD + d0 + c];
            wvS[r][c] = vw[r * DD + d0 + c];
        }
        __syncthreads();

#pragma unroll 8
        for (int d = 0; d < 32; d++) {
            const float x0 = xS[lrow + 0][d];
            const float x1 = xS[lrow + 1][d];
            const float x2 = xS[lrow + 2][d];
            const float x3 = xS[lrow + 3][d];
#pragma unroll
            for (int jj = 0; jj < 4; jj++) {
                const int e = lane + (jj << 5);
                const float wu = wuS[e][d];
                const float wv = wvS[e][d];
                qacc[0][jj] = fmaf(x0, wu, qacc[0][jj]);
                qacc[1][jj] = fmaf(x1, wu, qacc[1][jj]);
                qacc[2][jj] = fmaf(x2, wu, qacc[2][jj]);
                qacc[3][jj] = fmaf(x3, wu, qacc[3][jj]);
                kacc[0][jj] = fmaf(x0, wv, kacc[0][jj]);
                kacc[1][jj] = fmaf(x1, wv, kacc[1][jj]);
                kacc[2][jj] = fmaf(x2, wv, kacc[2][jj]);
                kacc[3][jj] = fmaf(x3, wv, kacc[3][jj]);
            }
        }
        __syncthreads();
    }

#pragma unroll
    for (int jj = 0; jj < 4; jj++) {
        const int e = lane + (jj << 5);
#pragma unroll
        for (int i = 0; i < 4; i++) {
            const int l = l0 + lrow + i;
            g_eq[((size_t)b * DD + e) * LL + l] = __expf(2.0f * qacc[i][jj]);
            g_ek[((size_t)b * LL + l) * DD + e] = __expf(2.0f * kacc[i][jj]);
        }
    }
}

// ---------------------------------------------------------------------------
// Kernel B: fused score + softmax + attn-write + out GEMM.
// tanh identity: sum_d a_d*tanh(q+k) = C - 2*sum_d a_d/(Eq_jd*Ek_id + 1),
// C constant over j -> dropped in softmax.
// Pair trick: a1/x1 + a2/x2 = (a1*x2 + a2*x1)/(x1*x2) -> ONE rcp per TWO d's.
// All scalar fp32: no packing, no integer ops, ALU stays idle.
// grid = 512 blocks, 512 threads (16 warps); warp w owns j in [32w,32w+32),
// runs all 128 d's (64 pairs) for 8 i-rows.
// Per (pair, ii): 1 LDS.64 + 6 FMA-class + 1 MUFU = 8 instrs / 64 lane-el.
// ---------------------------------------------------------------------------
__global__ __launch_bounds__(512, 2) void attn_kernel(
    const float* __restrict__ inp,
    const float* __restrict__ aw,
    float* __restrict__ out,
    float* __restrict__ attn)
{
    __shared__ __align__(16) float2 ekS[8][64];   // Ek d-pairs per i-row
    __shared__ __align__(16) float2 naS[64];      // (-a_{2p}, -a_{2p+1})
    __shared__ float sc[8][512];
    __shared__ __align__(16) float outS[2][8][128];

    const int b    = blockIdx.x >> 6;
    const int i0   = (blockIdx.x & 63) << 3;
    const int t    = threadIdx.x;
    const int lane = t & 31;
    const int w    = t >> 5;

    // Stage Ek pairs (rows are d-contiguous -> direct float2 loads) and -a pairs
    {
        const float2* __restrict__ ekrow =
            (const float2*)(g_ek + ((size_t)b * LL + i0) * DD);
        for (int idx = t; idx < 8 * 64; idx += 512)
            ekS[idx >> 6][idx & 63] = ekrow[idx];
    }
    if (t < 64) {
        const float2 a2 = ((const float2*)aw)[t];
        naS[t] = make_float2(-a2.x, -a2.y);
    }
    __syncthreads();

    // ---- Phase 2: acc[ii] = -sum_d a_d/(Eq*Ek+1)  (one rcp per d-pair) ----
    const int j = (w << 5) + lane;
    float acc[8];
#pragma unroll
    for (int ii = 0; ii < 8; ii++) acc[ii] = 0.f;

    const float* __restrict__ eqcol = g_eq + (size_t)b * DD * LL + j;

#pragma unroll 2
    for (int p = 0; p < 64; p++) {
        const float eq1 = eqcol[(size_t)(2 * p) * LL];       // coalesced 128B
        const float eq2 = eqcol[(size_t)(2 * p + 1) * LL];
        const float2 na = naS[p];                            // broadcast
#pragma unroll
        for (int ii = 0; ii < 8; ii++) {
            const float2 ek = ekS[ii][p];                    // LDS.64 broadcast
            const float x1 = fmaf(eq1, ek.x, 1.0f);
            const float x2 = fmaf(eq2, ek.y, 1.0f);
            const float m   = na.x * x2;
            const float num = fmaf(na.y, x1, m);             // -(a1*x2 + a2*x1)
            const float den = x1 * x2;
            const float r   = rcp_fast(den);
            acc[ii] = fmaf(num, r, acc[ii]);
        }
    }
#pragma unroll
    for (int ii = 0; ii < 8; ii++) sc[ii][j] = acc[ii];
    __syncthreads();

    // ---- Phase 3: softmax over j (score = 2*acc + const) ----
    if (w < 8) {
        const int r = w;
        float v[16];
        float mx = -1e30f;
#pragma unroll
        for (int q = 0; q < 16; q++) {
            const int jj = lane + (q << 5);
            v[q] = 2.0f * sc[r][jj];
            mx = fmaxf(mx, v[q]);
        }
#pragma unroll
        for (int o = 16; o > 0; o >>= 1) mx = fmaxf(mx, __shfl_xor_sync(0xffffffffu, mx, o));
        float s = 0.f;
#pragma unroll
        for (int q = 0; q < 16; q++) { v[q] = __expf(v[q] - mx); s += v[q]; }
#pragma unroll
        for (int o = 16; o > 0; o >>= 1) s += __shfl_xor_sync(0xffffffffu, s, o);
        const float inv = 1.0f / s;
        float* arow = attn + ((size_t)b * LL + i0 + r) * LL;
#pragma unroll
        for (int q = 0; q < 16; q++) {
            const int jj = lane + (q << 5);
            const float av = v[q] * inv;
            sc[r][jj] = av;       // reuse for GEMM
            arow[jj]  = av;       // coalesced attn output
        }
    }
    __syncthreads();

    // ---- Phase 4: out[i,:] = sum_j attn[i,j] * inp[b,j,:] ----
    {
        const int r = w & 7, hh = w >> 3;
        float4 racc = make_float4(0.f, 0.f, 0.f, 0.f);
        const float4* __restrict__ xin =
            (const float4*)(inp + (size_t)(b * LL + (hh << 8)) * DD) + lane;
#pragma unroll 8
        for (int jj = 0; jj < 256; jj++) {
            const float av = sc[r][(hh << 8) + jj];       // broadcast
            const float4 xv = xin[jj * (DD / 4)];         // coalesced LDG.128
            racc.x = fmaf(av, xv.x, racc.x);
            racc.y = fmaf(av, xv.y, racc.y);
            racc.z = fmaf(av, xv.z, racc.z);
            racc.w = fmaf(av, xv.w, racc.w);
        }
        *(float4*)&outS[hh][r][lane << 2] = racc;
    }
    __syncthreads();
    if (w < 8) {
        const int r = w;
        const float4 o0 = *(const float4*)&outS[0][r][lane << 2];
        const float4 o1 = *(const float4*)&outS[1][r][lane << 2];
        float4 o = make_float4(o0.x + o1.x, o0.y + o1.y, o0.z + o1.z, o0.w + o1.w);
        *(float4*)&out[((size_t)b * LL + i0 + r) * DD + (lane << 2)] = o;
    }
}

// ---------------------------------------------------------------------------
extern "C" void kernel_launch(void* const* d_in, const int* in_sizes, int n_in,
                              void* d_out, int out_size)
{
    const float* inp = (const float*)d_in[0];
    const float* uw  = (const float*)d_in[1];
    const float* vw  = (const float*)d_in[2];
    const float* aw  = (const float*)d_in[3];

    float* out  = (float*)d_out;
    float* attn = out + BB * LL * DD;

    proj_kernel<<<BB * (LL / 32), 256>>>(inp, uw, vw);
    attn_kernel<<<BB * (LL / 8), 512>>>(inp, aw, out, attn);
}

// round 9
// speedup vs baseline: 1.1789x; 1.1488x over previous
#include <cuda_runtime.h>

#define BB 8
#define LL 512
#define DD 128

// Scratch (allocation-free rule: __device__ globals)
__device__ float g_eq[BB * DD * LL];  // [b][d][l]  e^{2q}, l contiguous
__device__ float g_ek[BB * LL * DD];  // [b][l][d]  e^{2k}

__device__ __forceinline__ float rcp_fast(float x) {
    float y; asm("rcp.approx.f32 %0, %1;" : "=f"(y) : "f"(x)); return y;
}

// ---------------------------------------------------------------------------
// Kernel A: Eq = exp(2 * inp@u_w^T) stored transposed [b][d][l],
//           Ek = exp(2 * inp@v_w^T) row-major [b][l][d]
// ---------------------------------------------------------------------------
__global__ __launch_bounds__(256, 2) void proj_kernel(
    const float* __restrict__ inp,
    const float* __restrict__ uw,
    const float* __restrict__ vw)
{
    __shared__ float xS[32][32];
    __shared__ float wuS[128][33];
    __shared__ float wvS[128][33];

    const int b    = blockIdx.x >> 4;
    const int l0   = (blockIdx.x & 15) << 5;
    const int t    = threadIdx.x;
    const int lane = t & 31;
    const int warp = t >> 5;
    const int lrow = warp << 2;

    float qacc[4][4], kacc[4][4];
#pragma unroll
    for (int i = 0; i < 4; i++)
#pragma unroll
        for (int jj = 0; jj < 4; jj++) { qacc[i][jj] = 0.f; kacc[i][jj] = 0.f; }

    for (int kc = 0; kc < 4; kc++) {
        const int d0 = kc << 5;
        for (int idx = t; idx < 32 * 32; idx += 256) {
            int r = idx >> 5, c = idx & 31;
            xS[r][c] = inp[(b * LL + l0 + r) * DD + d0 + c];
        }
        for (int idx = t; idx < 128 * 32; idx += 256) {
            int r = idx >> 5, c = idx & 31;
            wuS[r][c] = uw[r * DD + d0 + c];
            wvS[r][c] = vw[r * DD + d0 + c];
        }
        __syncthreads();

#pragma unroll 8
        for (int d = 0; d < 32; d++) {
            const float x0 = xS[lrow + 0][d];
            const float x1 = xS[lrow + 1][d];
            const float x2 = xS[lrow + 2][d];
            const float x3 = xS[lrow + 3][d];
#pragma unroll
            for (int jj = 0; jj < 4; jj++) {
                const int e = lane + (jj << 5);
                const float wu = wuS[e][d];
                const float wv = wvS[e][d];
                qacc[0][jj] = fmaf(x0, wu, qacc[0][jj]);
                qacc[1][jj] = fmaf(x1, wu, qacc[1][jj]);
                qacc[2][jj] = fmaf(x2, wu, qacc[2][jj]);
                qacc[3][jj] = fmaf(x3, wu, qacc[3][jj]);
                kacc[0][jj] = fmaf(x0, wv, kacc[0][jj]);
                kacc[1][jj] = fmaf(x1, wv, kacc[1][jj]);
                kacc[2][jj] = fmaf(x2, wv, kacc[2][jj]);
                kacc[3][jj] = fmaf(x3, wv, kacc[3][jj]);
            }
        }
        __syncthreads();
    }

#pragma unroll
    for (int jj = 0; jj < 4; jj++) {
        const int e = lane + (jj << 5);
#pragma unroll
        for (int i = 0; i < 4; i++) {
            const int l = l0 + lrow + i;
            g_eq[((size_t)b * DD + e) * LL + l] = __expf(2.0f * qacc[i][jj]);
            g_ek[((size_t)b * LL + l) * DD + e] = __expf(2.0f * kacc[i][jj]);
        }
    }
}

// ---------------------------------------------------------------------------
// Kernel B: fused score + softmax + attn-write + out GEMM.
// Phase 2 (unchanged from v8): one rcp per d-pair, all scalar fp32.
// Phase 4 (new): dedup inp reads. Warp w: i-group ig=w>>3 (4 rows),
// j-chunk jc=w&7 (64 j's). Each inp row read by 2 warps (was 8).
// Partials reduced through a 16KB smem buffer (write / RMW / final-sum).
// ---------------------------------------------------------------------------
__global__ __launch_bounds__(512, 2) void attn_kernel(
    const float* __restrict__ inp,
    const float* __restrict__ aw,
    float* __restrict__ out,
    float* __restrict__ attn)
{
    union U {
        struct {                       // phase 2 staging (dead after phase 2)
            float2 ekS[8][64];         // Ek d-pairs per i-row
            float2 naS[64];            // (-a_{2p}, -a_{2p+1})
        } p2;
        float red[4][2][4][DD];        // phase 4 partials [jc&3][ig][i][d]
    };
    __shared__ __align__(16) U u;
    __shared__ float sc[8][512];       // scores -> attn weights

    const int b    = blockIdx.x >> 6;
    const int i0   = (blockIdx.x & 63) << 3;
    const int t    = threadIdx.x;
    const int lane = t & 31;
    const int w    = t >> 5;

    // Stage Ek pairs (d-contiguous rows -> direct float2 loads) and -a pairs
    {
        const float2* __restrict__ ekrow =
            (const float2*)(g_ek + ((size_t)b * LL + i0) * DD);
        for (int idx = t; idx < 8 * 64; idx += 512)
            u.p2.ekS[idx >> 6][idx & 63] = ekrow[idx];
    }
    if (t < 64) {
        const float2 a2 = ((const float2*)aw)[t];
        u.p2.naS[t] = make_float2(-a2.x, -a2.y);
    }
    __syncthreads();

    // ---- Phase 2: acc[ii] = -sum_d a_d/(Eq*Ek+1)  (one rcp per d-pair) ----
    {
        const int j = (w << 5) + lane;
        float acc[8];
#pragma unroll
        for (int ii = 0; ii < 8; ii++) acc[ii] = 0.f;

        const float* __restrict__ eqcol = g_eq + (size_t)b * DD * LL + j;

#pragma unroll 2
        for (int p = 0; p < 64; p++) {
            const float eq1 = eqcol[(size_t)(2 * p) * LL];       // coalesced 128B
            const float eq2 = eqcol[(size_t)(2 * p + 1) * LL];
            const float2 na = u.p2.naS[p];                       // broadcast
#pragma unroll
            for (int ii = 0; ii < 8; ii++) {
                const float2 ek = u.p2.ekS[ii][p];               // LDS.64 broadcast
                const float x1 = fmaf(eq1, ek.x, 1.0f);
                const float x2 = fmaf(eq2, ek.y, 1.0f);
                const float m   = na.x * x2;
                const float num = fmaf(na.y, x1, m);             // -(a1*x2 + a2*x1)
                const float den = x1 * x2;
                const float r   = rcp_fast(den);
                acc[ii] = fmaf(num, r, acc[ii]);
            }
        }
#pragma unroll
        for (int ii = 0; ii < 8; ii++) sc[ii][j] = acc[ii];
    }
    __syncthreads();   // ekS/naS dead beyond this point

    // ---- Phase 3: softmax over j (score = 2*acc + const) ----
    if (w < 8) {
        const int r = w;
        float v[16];
        float mx = -1e30f;
#pragma unroll
        for (int q = 0; q < 16; q++) {
            const int jj = lane + (q << 5);
            v[q] = 2.0f * sc[r][jj];
            mx = fmaxf(mx, v[q]);
        }
#pragma unroll
        for (int o = 16; o > 0; o >>= 1) mx = fmaxf(mx, __shfl_xor_sync(0xffffffffu, mx, o));
        float s = 0.f;
#pragma unroll
        for (int q = 0; q < 16; q++) { v[q] = __expf(v[q] - mx); s += v[q]; }
#pragma unroll
        for (int o = 16; o > 0; o >>= 1) s += __shfl_xor_sync(0xffffffffu, s, o);
        const float inv = 1.0f / s;
        float* arow = attn + ((size_t)b * LL + i0 + r) * LL;
#pragma unroll
        for (int q = 0; q < 16; q++) {
            const int jj = lane + (q << 5);
            const float av = v[q] * inv;
            sc[r][jj] = av;       // reuse for phase 4
            arow[jj]  = av;       // coalesced attn output
        }
    }
    __syncthreads();

    // ---- Phase 4a: partial out over 64 j's for 4 i-rows per warp ----
    const int ig = w >> 3;   // i-group: rows ig*4 .. ig*4+3
    const int jc = w & 7;    // j-chunk: [jc*64, jc*64+64)
    {
        float4 a0 = make_float4(0.f,0.f,0.f,0.f);
        float4 a1 = a0, a2 = a0, a3 = a0;
        const float4* __restrict__ xin =
            (const float4*)(inp + ((size_t)b * LL + (jc << 6)) * DD) + lane;
        const float* __restrict__ s0 = &sc[(ig << 2) + 0][jc << 6];
        const float* __restrict__ s1 = &sc[(ig << 2) + 1][jc << 6];
        const float* __restrict__ s2 = &sc[(ig << 2) + 2][jc << 6];
        const float* __restrict__ s3 = &sc[(ig << 2) + 3][jc << 6];
#pragma unroll 4
        for (int jj = 0; jj < 64; jj++) {
            const float4 xv = xin[jj * (DD / 4)];   // coalesced LDG.128, 2x dedup
            const float w0 = s0[jj];                // broadcast LDS
            const float w1 = s1[jj];
            const float w2 = s2[jj];
            const float w3 = s3[jj];
            a0.x = fmaf(w0, xv.x, a0.x); a0.y = fmaf(w0, xv.y, a0.y);
            a0.z = fmaf(w0, xv.z, a0.z); a0.w = fmaf(w0, xv.w, a0.w);
            a1.x = fmaf(w1, xv.x, a1.x); a1.y = fmaf(w1, xv.y, a1.y);
            a1.z = fmaf(w1, xv.z, a1.z); a1.w = fmaf(w1, xv.w, a1.w);
            a2.x = fmaf(w2, xv.x, a2.x); a2.y = fmaf(w2, xv.y, a2.y);
            a2.z = fmaf(w2, xv.z, a2.z); a2.w = fmaf(w2, xv.w, a2.w);
            a3.x = fmaf(w3, xv.x, a3.x); a3.y = fmaf(w3, xv.y, a3.y);
            a3.z = fmaf(w3, xv.z, a3.z); a3.w = fmaf(w3, xv.w, a3.w);
        }
        // jc<4 warps seed the buffer; jc>=4 warps hold their acc for the RMW
        if (jc < 4) {
            *(float4*)&u.red[jc][ig][0][lane << 2] = a0;
            *(float4*)&u.red[jc][ig][1][lane << 2] = a1;
            *(float4*)&u.red[jc][ig][2][lane << 2] = a2;
            *(float4*)&u.red[jc][ig][3][lane << 2] = a3;
        }
        __syncthreads();
        if (jc >= 4) {
            const int c = jc - 4;
            float4* p0 = (float4*)&u.red[c][ig][0][lane << 2];
            float4* p1 = (float4*)&u.red[c][ig][1][lane << 2];
            float4* p2 = (float4*)&u.red[c][ig][2][lane << 2];
            float4* p3 = (float4*)&u.red[c][ig][3][lane << 2];
            float4 c0 = *p0, c1 = *p1, c2 = *p2, c3 = *p3;
            c0.x += a0.x; c0.y += a0.y; c0.z += a0.z; c0.w += a0.w;
            c1.x += a1.x; c1.y += a1.y; c1.z += a1.z; c1.w += a1.w;
            c2.x += a2.x; c2.y += a2.y; c2.z += a2.z; c2.w += a2.w;
            c3.x += a3.x; c3.y += a3.y; c3.z += a3.z; c3.w += a3.w;
            *p0 = c0; *p1 = c1; *p2 = c2; *p3 = c3;
        }
    }
    __syncthreads();

    // ---- Phase 4b: final 4-way sum + store (one warp per i-row) ----
    if (w < 8) {
        const int r  = w;
        const int gg = r >> 2;
        const int ir = r & 3;
        const float4 v0 = *(const float4*)&u.red[0][gg][ir][lane << 2];
        const float4 v1 = *(const float4*)&u.red[1][gg][ir][lane << 2];
        const float4 v2 = *(const float4*)&u.red[2][gg][ir][lane << 2];
        const float4 v3 = *(const float4*)&u.red[3][gg][ir][lane << 2];
        float4 o;
        o.x = (v0.x + v1.x) + (v2.x + v3.x);
        o.y = (v0.y + v1.y) + (v2.y + v3.y);
        o.z = (v0.z + v1.z) + (v2.z + v3.z);
        o.w = (v0.w + v1.w) + (v2.w + v3.w);
        *(float4*)&out[((size_t)b * LL + i0 + r) * DD + (lane << 2)] = o;
    }
}

// ---------------------------------------------------------------------------
extern "C" void kernel_launch(void* const* d_in, const int* in_sizes, int n_in,
                              void* d_out, int out_size)
{
    const float* inp = (const float*)d_in[0];
    const float* uw  = (const float*)d_in[1];
    const float* vw  = (const float*)d_in[2];
    const float* aw  = (const float*)d_in[3];

    float* out  = (float*)d_out;
    float* attn = out + BB * LL * DD;

    proj_kernel<<<BB * (LL / 32), 256>>>(inp, uw, vw);
    attn_kernel<<<BB * (LL / 8), 512>>>(inp, aw, out, attn);
}

// round 10
// speedup vs baseline: 1.1834x; 1.0038x over previous
#include <cuda_runtime.h>

#define BB 8
#define LL 512
#define DD 128

// Scratch (allocation-free rule: __device__ globals)
__device__ float g_eq[BB * DD * LL];  // [b][d][l]  e^{2q}, l contiguous
__device__ float g_ek[BB * LL * DD];  // [b][l][d]  e^{2k}

__device__ __forceinline__ float rcp_fast(float x) {
    float y; asm("rcp.approx.f32 %0, %1;" : "=f"(y) : "f"(x)); return y;
}

// ---------------------------------------------------------------------------
// Kernel A: Eq = exp(2 * inp@u_w^T) stored transposed [b][d][l],
//           Ek = exp(2 * inp@v_w^T) row-major [b][l][d]
// ---------------------------------------------------------------------------
__global__ __launch_bounds__(256, 2) void proj_kernel(
    const float* __restrict__ inp,
    const float* __restrict__ uw,
    const float* __restrict__ vw)
{
    __shared__ float xS[32][32];
    __shared__ float wuS[128][33];
    __shared__ float wvS[128][33];

    const int b    = blockIdx.x >> 4;
    const int l0   = (blockIdx.x & 15) << 5;
    const int t    = threadIdx.x;
    const int lane = t & 31;
    const int warp = t >> 5;
    const int lrow = warp << 2;

    float qacc[4][4], kacc[4][4];
#pragma unroll
    for (int i = 0; i < 4; i++)
#pragma unroll
        for (int jj = 0; jj < 4; jj++) { qacc[i][jj] = 0.f; kacc[i][jj] = 0.f; }

    for (int kc = 0; kc < 4; kc++) {
        const int d0 = kc << 5;
        for (int idx = t; idx < 32 * 32; idx += 256) {
            int r = idx >> 5, c = idx & 31;
            xS[r][c] = inp[(b * LL + l0 + r) * DD + d0 + c];
        }
        for (int idx = t; idx < 128 * 32; idx += 256) {
            int r = idx >> 5, c = idx & 31;
            wuS[r][c] = uw[r * DD + d0 + c];
            wvS[r][c] = vw[r * DD + d0 + c];
        }
        __syncthreads();

#pragma unroll 8
        for (int d = 0; d < 32; d++) {
            const float x0 = xS[lrow + 0][d];
            const float x1 = xS[lrow + 1][d];
            const float x2 = xS[lrow + 2][d];
            const float x3 = xS[lrow + 3][d];
#pragma unroll
            for (int jj = 0; jj < 4; jj++) {
                const int e = lane + (jj << 5);
                const float wu = wuS[e][d];
                const float wv = wvS[e][d];
                qacc[0][jj] = fmaf(x0, wu, qacc[0][jj]);
                qacc[1][jj] = fmaf(x1, wu, qacc[1][jj]);
                qacc[2][jj] = fmaf(x2, wu, qacc[2][jj]);
                qacc[3][jj] = fmaf(x3, wu, qacc[3][jj]);
                kacc[0][jj] = fmaf(x0, wv, kacc[0][jj]);
                kacc[1][jj] = fmaf(x1, wv, kacc[1][jj]);
                kacc[2][jj] = fmaf(x2, wv, kacc[2][jj]);
                kacc[3][jj] = fmaf(x3, wv, kacc[3][jj]);
            }
        }
        __syncthreads();
    }

#pragma unroll
    for (int jj = 0; jj < 4; jj++) {
        const int e = lane + (jj << 5);
#pragma unroll
        for (int i = 0; i < 4; i++) {
            const int l = l0 + lrow + i;
            g_eq[((size_t)b * DD + e) * LL + l] = __expf(2.0f * qacc[i][jj]);
            g_ek[((size_t)b * LL + l) * DD + e] = __expf(2.0f * kacc[i][jj]);
        }
    }
}

// ---------------------------------------------------------------------------
// Kernel B: fused score + softmax + attn-write + out GEMM.
// Phase 2: d-quads. Per (quad, ii): 1 LDS.128 + 4 FFMA + 6 combine + 2 rcp
//          + 2 acc = 15 instrs / 4 elements (one rcp per d-pair).
// Phase 4: 2x-dedup inp reads + float2 weight loads.
// ---------------------------------------------------------------------------
__global__ __launch_bounds__(512, 2) void attn_kernel(
    const float* __restrict__ inp,
    const float* __restrict__ aw,
    float* __restrict__ out,
    float* __restrict__ attn)
{
    union U {
        struct {                       // phase 2 staging (dead after phase 2)
            float4 ekS[8][32];         // Ek d-quads per i-row
            float4 naS[32];            // (-a_{4p..4p+3})
        } p2;
        float red[4][2][4][DD];        // phase 4 partials [chunk][ig][i][d]
    };
    __shared__ __align__(16) U u;
    __shared__ float sc[8][512];       // scores -> attn weights

    const int b    = blockIdx.x >> 6;
    const int i0   = (blockIdx.x & 63) << 3;
    const int t    = threadIdx.x;
    const int lane = t & 31;
    const int w    = t >> 5;

    // Stage Ek quads (d-contiguous rows -> direct float4 loads) and -a quads
    {
        const float4* __restrict__ ekrow =
            (const float4*)(g_ek + ((size_t)b * LL + i0) * DD);
        for (int idx = t; idx < 8 * 32; idx += 512)
            u.p2.ekS[idx >> 5][idx & 31] = ekrow[idx];
    }
    if (t < 32) {
        const float4 a4 = ((const float4*)aw)[t];
        u.p2.naS[t] = make_float4(-a4.x, -a4.y, -a4.z, -a4.w);
    }
    __syncthreads();

    // ---- Phase 2: acc[ii] = -sum_d a_d/(Eq*Ek+1) ----
    {
        const int j = (w << 5) + lane;
        float acc[8];
#pragma unroll
        for (int ii = 0; ii < 8; ii++) acc[ii] = 0.f;

        const float* __restrict__ eqcol = g_eq + (size_t)b * DD * LL + j;

#pragma unroll 2
        for (int p = 0; p < 32; p++) {
            const float eq0 = eqcol[(size_t)(4 * p + 0) * LL];   // coalesced 128B
            const float eq1 = eqcol[(size_t)(4 * p + 1) * LL];
            const float eq2 = eqcol[(size_t)(4 * p + 2) * LL];
            const float eq3 = eqcol[(size_t)(4 * p + 3) * LL];
            const float4 na = u.p2.naS[p];                       // LDS.128 broadcast
#pragma unroll
            for (int ii = 0; ii < 8; ii++) {
                const float4 ek = u.p2.ekS[ii][p];               // LDS.128 broadcast
                const float x1 = fmaf(eq0, ek.x, 1.0f);
                const float x2 = fmaf(eq1, ek.y, 1.0f);
                const float x3 = fmaf(eq2, ek.z, 1.0f);
                const float x4 = fmaf(eq3, ek.w, 1.0f);
                // pair A: (-a0)/x1 + (-a1)/x2
                const float mA   = na.x * x2;
                const float numA = fmaf(na.y, x1, mA);
                const float denA = x1 * x2;
                // pair B: (-a2)/x3 + (-a3)/x4
                const float mB   = na.z * x4;
                const float numB = fmaf(na.w, x3, mB);
                const float denB = x3 * x4;
                const float rA = rcp_fast(denA);
                const float rB = rcp_fast(denB);
                acc[ii] = fmaf(numA, rA, acc[ii]);
                acc[ii] = fmaf(numB, rB, acc[ii]);
            }
        }
#pragma unroll
        for (int ii = 0; ii < 8; ii++) sc[ii][j] = acc[ii];
    }
    __syncthreads();   // ekS/naS dead beyond this point

    // ---- Phase 3: softmax over j (score = 2*acc + const) ----
    if (w < 8) {
        const int r = w;
        float v[16];
        float mx = -1e30f;
#pragma unroll
        for (int q = 0; q < 16; q++) {
            const int jj = lane + (q << 5);
            v[q] = 2.0f * sc[r][jj];
            mx = fmaxf(mx, v[q]);
        }
#pragma unroll
        for (int o = 16; o > 0; o >>= 1) mx = fmaxf(mx, __shfl_xor_sync(0xffffffffu, mx, o));
        float s = 0.f;
#pragma unroll
        for (int q = 0; q < 16; q++) { v[q] = __expf(v[q] - mx); s += v[q]; }
#pragma unroll
        for (int o = 16; o > 0; o >>= 1) s += __shfl_xor_sync(0xffffffffu, s, o);
        const float inv = 1.0f / s;
        float* arow = attn + ((size_t)b * LL + i0 + r) * LL;
#pragma unroll
        for (int q = 0; q < 16; q++) {
            const int jj = lane + (q << 5);
            const float av = v[q] * inv;
            sc[r][jj] = av;       // reuse for phase 4
            arow[jj]  = av;       // coalesced attn output
        }
    }
    __syncthreads();

    // ---- Phase 4a: partial out over 64 j's for 4 i-rows per warp ----
    const int ig = w >> 3;   // i-group: rows ig*4 .. ig*4+3
    const int jc = w & 7;    // j-chunk: [jc*64, jc*64+64)
    {
        float4 a0 = make_float4(0.f,0.f,0.f,0.f);
        float4 a1 = a0, a2 = a0, a3 = a0;
        const float4* __restrict__ xin =
            (const float4*)(inp + ((size_t)b * LL + (jc << 6)) * DD) + lane;
        const float2* __restrict__ s0 = (const float2*)&sc[(ig << 2) + 0][jc << 6];
        const float2* __restrict__ s1 = (const float2*)&sc[(ig << 2) + 1][jc << 6];
        const float2* __restrict__ s2 = (const float2*)&sc[(ig << 2) + 2][jc << 6];
        const float2* __restrict__ s3 = (const float2*)&sc[(ig << 2) + 3][jc << 6];
#pragma unroll 4
        for (int jj = 0; jj < 32; jj++) {
            const float2 w0 = s0[jj];                   // LDS.64 broadcast, 2 j's
            const float2 w1 = s1[jj];
            const float2 w2 = s2[jj];
            const float2 w3 = s3[jj];
            const float4 xa = xin[(2 * jj + 0) * (DD / 4)];   // coalesced LDG.128
            a0.x = fmaf(w0.x, xa.x, a0.x); a0.y = fmaf(w0.x, xa.y, a0.y);
            a0.z = fmaf(w0.x, xa.z, a0.z); a0.w = fmaf(w0.x, xa.w, a0.w);
            a1.x = fmaf(w1.x, xa.x, a1.x); a1.y = fmaf(w1.x, xa.y, a1.y);
            a1.z = fmaf(w1.x, xa.z, a1.z); a1.w = fmaf(w1.x, xa.w, a1.w);
            a2.x = fmaf(w2.x, xa.x, a2.x); a2.y = fmaf(w2.x, xa.y, a2.y);
            a2.z = fmaf(w2.x, xa.z, a2.z); a2.w = fmaf(w2.x, xa.w, a2.w);
            a3.x = fmaf(w3.x, xa.x, a3.x); a3.y = fmaf(w3.x, xa.y, a3.y);
            a3.z = fmaf(w3.x, xa.z, a3.z); a3.w = fmaf(w3.x, xa.w, a3.w);
            const float4 xb = xin[(2 * jj + 1) * (DD / 4)];
            a0.x = fmaf(w0.y, xb.x, a0.x); a0.y = fmaf(w0.y, xb.y, a0.y);
            a0.z = fmaf(w0.y, xb.z, a0.z); a0.w = fmaf(w0.y, xb.w, a0.w);
            a1.x = fmaf(w1.y, xb.x, a1.x); a1.y = fmaf(w1.y, xb.y, a1.y);
            a1.z = fmaf(w1.y, xb.z, a1.z); a1.w = fmaf(w1.y, xb.w, a1.w);
            a2.x = fmaf(w2.y, xb.x, a2.x); a2.y = fmaf(w2.y, xb.y, a2.y);
            a2.z = fmaf(w2.y, xb.z, a2.z); a2.w = fmaf(w2.y, xb.w, a2.w);
            a3.x = fmaf(w3.y, xb.x, a3.x); a3.y = fmaf(w3.y, xb.y, a3.y);
            a3.z = fmaf(w3.y, xb.z, a3.z); a3.w = fmaf(w3.y, xb.w, a3.w);
        }
        // jc<4 warps seed the buffer; jc>=4 warps hold their acc for the RMW
        if (jc < 4) {
            *(float4*)&u.red[jc][ig][0][lane << 2] = a0;
            *(float4*)&u.red[jc][ig][1][lane << 2] = a1;
            *(float4*)&u.red[jc][ig][2][lane << 2] = a2;
            *(float4*)&u.red[jc][ig][3][lane << 2] = a3;
        }
        __syncthreads();
        if (jc >= 4) {
            const int c = jc - 4;
            float4* p0 = (float4*)&u.red[c][ig][0][lane << 2];
            float4* p1 = (float4*)&u.red[c][ig][1][lane << 2];
            float4* p2 = (float4*)&u.red[c][ig][2][lane << 2];
            float4* p3 = (float4*)&u.red[c][ig][3][lane << 2];
            float4 c0 = *p0, c1 = *p1, c2 = *p2, c3 = *p3;
            c0.x += a0.x; c0.y += a0.y; c0.z += a0.z; c0.w += a0.w;
            c1.x += a1.x; c1.y += a1.y; c1.z += a1.z; c1.w += a1.w;
            c2.x += a2.x; c2.y += a2.y; c2.z += a2.z; c2.w += a2.w;
            c3.x += a3.x; c3.y += a3.y; c3.z += a3.z; c3.w += a3.w;
            *p0 = c0; *p1 = c1; *p2 = c2; *p3 = c3;
        }
    }
    __syncthreads();

    // ---- Phase 4b: final 4-way sum + store (one warp per i-row) ----
    if (w < 8) {
        const int r  = w;
        const int gg = r >> 2;
        const int ir = r & 3;
        const float4 v0 = *(const float4*)&u.red[0][gg][ir][lane << 2];
        const float4 v1 = *(const float4*)&u.red[1][gg][ir][lane << 2];
        const float4 v2 = *(const float4*)&u.red[2][gg][ir][lane << 2];
        const float4 v3 = *(const float4*)&u.red[3][gg][ir][lane << 2];
        float4 o;
        o.x = (v0.x + v1.x) + (v2.x + v3.x);
        o.y = (v0.y + v1.y) + (v2.y + v3.y);
        o.z = (v0.z + v1.z) + (v2.z + v3.z);
        o.w = (v0.w + v1.w) + (v2.w + v3.w);
        *(float4*)&out[((size_t)b * LL + i0 + r) * DD + (lane << 2)] = o;
    }
}

// ---------------------------------------------------------------------------
extern "C" void kernel_launch(void* const* d_in, const int* in_sizes, int n_in,
                              void* d_out, int out_size)
{
    const float* inp = (const float*)d_in[0];
    const float* uw  = (const float*)d_in[1];
    const float* vw  = (const float*)d_in[2];
    const float* aw  = (const float*)d_in[3];

    float* out  = (float*)d_out;
    float* attn = out + BB * LL * DD;

    proj_kernel<<<BB * (LL / 32), 256>>>(inp, uw, vw);
    attn_kernel<<<BB * (LL / 8), 512>>>(inp, aw, out, attn);
}

// round 11
// speedup vs baseline: 1.2330x; 1.0419x over previous
#include <cuda_runtime.h>

#define BB 8
#define LL 512
#define DD 128

typedef unsigned long long ull;

// Scratch (allocation-free rule: __device__ globals)
__device__ float g_eq[BB * DD * LL];  // [b][d][l]  e^{2q}, l contiguous
__device__ float g_ek[BB * LL * DD];  // [b][l][d]  e^{2k}

// ---- packed f32x2 helpers (sm_100a) ----
__device__ __forceinline__ ull fma2(ull a, ull b, ull c) {
    ull d; asm("fma.rn.f32x2 %0, %1, %2, %3;" : "=l"(d) : "l"(a), "l"(b), "l"(c)); return d;
}
__device__ __forceinline__ ull mul2(ull a, ull b) {
    ull d; asm("mul.rn.f32x2 %0, %1, %2;" : "=l"(d) : "l"(a), "l"(b)); return d;
}
__device__ __forceinline__ ull rcp2(ull x) {   // rcp of both packed halves
    ull y;
    asm("{\n\t.reg .f32 lo, hi;\n\t"
        "mov.b64 {lo, hi}, %1;\n\t"
        "rcp.approx.f32 lo, lo;\n\t"
        "rcp.approx.f32 hi, hi;\n\t"
        "mov.b64 %0, {lo, hi};\n\t}"
        : "=l"(y) : "l"(x));
    return y;
}
__device__ __forceinline__ ull dup_f32(float v) {
    ull d; asm("mov.b64 %0, {%1, %1};" : "=l"(d) : "f"(v)); return d;
}

#define ONE2 0x3F8000003F800000ULL

// ---------------------------------------------------------------------------
// Kernel A: Eq = exp(2 * inp@u_w^T) stored transposed [b][d][l],
//           Ek = exp(2 * inp@v_w^T) row-major [b][l][d]
// ---------------------------------------------------------------------------
__global__ __launch_bounds__(256, 2) void proj_kernel(
    const float* __restrict__ inp,
    const float* __restrict__ uw,
    const float* __restrict__ vw)
{
    __shared__ float xS[32][32];
    __shared__ float wuS[128][33];
    __shared__ float wvS[128][33];

    const int b    = blockIdx.x >> 4;
    const int l0   = (blockIdx.x & 15) << 5;
    const int t    = threadIdx.x;
    const int lane = t & 31;
    const int warp = t >> 5;
    const int lrow = warp << 2;

    float qacc[4][4], kacc[4][4];
#pragma unroll
    for (int i = 0; i < 4; i++)
#pragma unroll
        for (int jj = 0; jj < 4; jj++) { qacc[i][jj] = 0.f; kacc[i][jj] = 0.f; }

    for (int kc = 0; kc < 4; kc++) {
        const int d0 = kc << 5;
        for (int idx = t; idx < 32 * 32; idx += 256) {
            int r = idx >> 5, c = idx & 31;
            xS[r][c] = inp[(b * LL + l0 + r) * DD + d0 + c];
        }
        for (int idx = t; idx < 128 * 32; idx += 256) {
            int r = idx >> 5, c = idx & 31;
            wuS[r][c] = uw[r * DD + d0 + c];
            wvS[r][c] = vw[r * DD + d0 + c];
        }
        __syncthreads();

#pragma unroll 8
        for (int d = 0; d < 32; d++) {
            const float x0 = xS[lrow + 0][d];
            const float x1 = xS[lrow + 1][d];
            const float x2 = xS[lrow + 2][d];
            const float x3 = xS[lrow + 3][d];
#pragma unroll
            for (int jj = 0; jj < 4; jj++) {
                const int e = lane + (jj << 5);
                const float wu = wuS[e][d];
                const float wv = wvS[e][d];
                qacc[0][jj] = fmaf(x0, wu, qacc[0][jj]);
                qacc[1][jj] = fmaf(x1, wu, qacc[1][jj]);
                qacc[2][jj] = fmaf(x2, wu, qacc[2][jj]);
                qacc[3][jj] = fmaf(x3, wu, qacc[3][jj]);
                kacc[0][jj] = fmaf(x0, wv, kacc[0][jj]);
                kacc[1][jj] = fmaf(x1, wv, kacc[1][jj]);
                kacc[2][jj] = fmaf(x2, wv, kacc[2][jj]);
                kacc[3][jj] = fmaf(x3, wv, kacc[3][jj]);
            }
        }
        __syncthreads();
    }

#pragma unroll
    for (int jj = 0; jj < 4; jj++) {
        const int e = lane + (jj << 5);
#pragma unroll
        for (int i = 0; i < 4; i++) {
            const int l = l0 + lrow + i;
            g_eq[((size_t)b * DD + e) * LL + l] = __expf(2.0f * qacc[i][jj]);
            g_ek[((size_t)b * LL + l) * DD + e] = __expf(2.0f * kacc[i][jj]);
        }
    }
}

// ---------------------------------------------------------------------------
// Kernel B: fused score + softmax + attn-write + out GEMM.
// Phase 2 in packed f32x2 over j-pairs: lane owns (j, j+1); Ek and -a are
// duplicated into both 64-bit lanes AT STAGING (no pack instrs in the loop).
// Pair-combine per 2 d's: one rcp per d-pair, all else fma2/mul2.
// Warps: h = d-half (2) x jc = 64-j tile (8). Partials in sc / scp1.
// Phase 4: 2x-dedup inp reads (as R10), red buffer overlays phase-2 staging.
// ---------------------------------------------------------------------------
__global__ __launch_bounds__(512, 2) void attn_kernel(
    const float* __restrict__ inp,
    const float* __restrict__ aw,
    float* __restrict__ out,
    float* __restrict__ attn)
{
    union U {
        struct {                        // alive through phase 3
            ulonglong2 ekD[8][64];      // Ek dup'd: [ii][d/2] = (dup d, dup d+1)
            ulonglong2 naD[64];         // -a dup'd pairs
            float scp1[8][512];         // h=1 partial scores
        } p2;
        float red[4][2][4][DD];         // phase 4 partials (overlays p2)
    };
    __shared__ __align__(16) U u;
    __shared__ float sc[8][512];        // h=0 partials -> attn weights

    const int b    = blockIdx.x >> 6;
    const int i0   = (blockIdx.x & 63) << 3;
    const int t    = threadIdx.x;
    const int lane = t & 31;
    const int w    = t >> 5;

    // Stage Ek (duplicated pairs) and -a (duplicated pairs)
    {
        const float* __restrict__ ekbase = g_ek + ((size_t)b * LL + i0) * DD;
        for (int idx = t; idx < 8 * 64; idx += 512) {
            const int ii = idx >> 6, dp = idx & 63;
            const float2 kv = *(const float2*)(ekbase + ii * DD + (dp << 1));
            u.p2.ekD[ii][dp] = make_ulonglong2(dup_f32(kv.x), dup_f32(kv.y));
        }
    }
    if (t < 64) {
        const float2 a2 = ((const float2*)aw)[t];
        u.p2.naD[t] = make_ulonglong2(dup_f32(-a2.x), dup_f32(-a2.y));
    }
    __syncthreads();

    // ---- Phase 2: partial -sum_d a_d/(Eq*Ek+1) over this warp's d-half ----
    const int h     = w >> 3;            // d-half
    const int jc    = w & 7;             // 64-j tile
    const int jb    = jc << 6;
    const int dbase = h << 6;

    ull acc2[8];
#pragma unroll
    for (int ii = 0; ii < 8; ii++) acc2[ii] = 0ULL;

    // float2 view of g_eq: row d has LL/2 float2s; lane owns pair (jb+2*lane)
    const float2* __restrict__ eqp2 =
        (const float2*)g_eq + (size_t)b * DD * (LL >> 1) + (jb >> 1) + lane;

#pragma unroll 2
    for (int p = 0; p < 16; p++) {
        const int d0 = dbase + (p << 2);
        const ull eqA = *(const ull*)(eqp2 + (size_t)(d0 + 0) * (LL >> 1));
        const ull eqB = *(const ull*)(eqp2 + (size_t)(d0 + 1) * (LL >> 1));
        const ull eqC = *(const ull*)(eqp2 + (size_t)(d0 + 2) * (LL >> 1));
        const ull eqD = *(const ull*)(eqp2 + (size_t)(d0 + 3) * (LL >> 1));
        const ulonglong2 naAB = u.p2.naD[(d0 >> 1) + 0];   // LDS.128 broadcast
        const ulonglong2 naCD = u.p2.naD[(d0 >> 1) + 1];
#pragma unroll
        for (int ii = 0; ii < 8; ii++) {
            const ulonglong2 ekAB = u.p2.ekD[ii][(d0 >> 1) + 0];  // LDS.128
            const ulonglong2 ekCD = u.p2.ekD[ii][(d0 >> 1) + 1];
            // pair (d0, d0+1): 2 j's per lane -> 4 elements
            {
                const ull x1  = fma2(eqA, ekAB.x, ONE2);
                const ull x2  = fma2(eqB, ekAB.y, ONE2);
                const ull m   = mul2(naAB.x, x2);
                const ull num = fma2(naAB.y, x1, m);
                const ull den = mul2(x1, x2);
                const ull r   = rcp2(den);
                acc2[ii] = fma2(num, r, acc2[ii]);
            }
            // pair (d0+2, d0+3)
            {
                const ull x1  = fma2(eqC, ekCD.x, ONE2);
                const ull x2  = fma2(eqD, ekCD.y, ONE2);
                const ull m   = mul2(naCD.x, x2);
                const ull num = fma2(naCD.y, x1, m);
                const ull den = mul2(x1, x2);
                const ull r   = rcp2(den);
                acc2[ii] = fma2(num, r, acc2[ii]);
            }
        }
    }
    {
        float (* __restrict__ dst)[512] = (h == 0) ? sc : u.p2.scp1;
        const int j = jb + (lane << 1);
#pragma unroll
        for (int ii = 0; ii < 8; ii++)
            *(ull*)&dst[ii][j] = acc2[ii];    // STS.64, (j, j+1) adjacent
    }
    __syncthreads();

    // ---- Phase 3: softmax over j (score = 2*(sc + scp1) + const) ----
    if (w < 8) {
        const int r = w;
        float v[16];
        float mx = -1e30f;
#pragma unroll
        for (int q = 0; q < 16; q++) {
            const int jj = lane + (q << 5);
            v[q] = 2.0f * (sc[r][jj] + u.p2.scp1[r][jj]);
            mx = fmaxf(mx, v[q]);
        }
#pragma unroll
        for (int o = 16; o > 0; o >>= 1) mx = fmaxf(mx, __shfl_xor_sync(0xffffffffu, mx, o));
        float s = 0.f;
#pragma unroll
        for (int q = 0; q < 16; q++) { v[q] = __expf(v[q] - mx); s += v[q]; }
#pragma unroll
        for (int o = 16; o > 0; o >>= 1) s += __shfl_xor_sync(0xffffffffu, s, o);
        const float inv = 1.0f / s;
        float* arow = attn + ((size_t)b * LL + i0 + r) * LL;
#pragma unroll
        for (int q = 0; q < 16; q++) {
            const int jj = lane + (q << 5);
            const float av = v[q] * inv;
            sc[r][jj] = av;       // reuse for phase 4
            arow[jj]  = av;       // coalesced attn output
        }
    }
    __syncthreads();   // scp1/staging dead beyond this point -> red may overlay

    // ---- Phase 4a: partial out over 64 j's for 4 i-rows per warp ----
    const int ig = w >> 3;   // i-group: rows ig*4 .. ig*4+3
    const int cjc = w & 7;   // j-chunk: [cjc*64, cjc*64+64)
    {
        float4 a0 = make_float4(0.f,0.f,0.f,0.f);
        float4 a1 = a0, a2 = a0, a3 = a0;
        const float4* __restrict__ xin =
            (const float4*)(inp + ((size_t)b * LL + (cjc << 6)) * DD) + lane;
        const float2* __restrict__ s0 = (const float2*)&sc[(ig << 2) + 0][cjc << 6];
        const float2* __restrict__ s1 = (const float2*)&sc[(ig << 2) + 1][cjc << 6];
        const float2* __restrict__ s2 = (const float2*)&sc[(ig << 2) + 2][cjc << 6];
        const float2* __restrict__ s3 = (const float2*)&sc[(ig << 2) + 3][cjc << 6];
#pragma unroll 4
        for (int jj = 0; jj < 32; jj++) {
            const float2 w0 = s0[jj];
            const float2 w1 = s1[jj];
            const float2 w2 = s2[jj];
            const float2 w3 = s3[jj];
            const float4 xa = xin[(2 * jj + 0) * (DD / 4)];
            a0.x = fmaf(w0.x, xa.x, a0.x); a0.y = fmaf(w0.x, xa.y, a0.y);
            a0.z = fmaf(w0.x, xa.z, a0.z); a0.w = fmaf(w0.x, xa.w, a0.w);
            a1.x = fmaf(w1.x, xa.x, a1.x); a1.y = fmaf(w1.x, xa.y, a1.y);
            a1.z = fmaf(w1.x, xa.z, a1.z); a1.w = fmaf(w1.x, xa.w, a1.w);
            a2.x = fmaf(w2.x, xa.x, a2.x); a2.y = fmaf(w2.x, xa.y, a2.y);
            a2.z = fmaf(w2.x, xa.z, a2.z); a2.w = fmaf(w2.x, xa.w, a2.w);
            a3.x = fmaf(w3.x, xa.x, a3.x); a3.y = fmaf(w3.x, xa.y, a3.y);
            a3.z = fmaf(w3.x, xa.z, a3.z); a3.w = fmaf(w3.x, xa.w, a3.w);
            const float4 xb = xin[(2 * jj + 1) * (DD / 4)];
            a0.x = fmaf(w0.y, xb.x, a0.x); a0.y = fmaf(w0.y, xb.y, a0.y);
            a0.z = fmaf(w0.y, xb.z, a0.z); a0.w = fmaf(w0.y, xb.w, a0.w);
            a1.x = fmaf(w1.y, xb.x, a1.x); a1.y = fmaf(w1.y, xb.y, a1.y);
            a1.z = fmaf(w1.y, xb.z, a1.z); a1.w = fmaf(w1.y, xb.w, a1.w);
            a2.x = fmaf(w2.y, xb.x, a2.x); a2.y = fmaf(w2.y, xb.y, a2.y);
            a2.z = fmaf(w2.y, xb.z, a2.z); a2.w = fmaf(w2.y, xb.w, a2.w);
            a3.x = fmaf(w3.y, xb.x, a3.x); a3.y = fmaf(w3.y, xb.y, a3.y);
            a3.z = fmaf(w3.y, xb.z, a3.z); a3.w = fmaf(w3.y, xb.w, a3.w);
        }
        if (cjc < 4) {
            *(float4*)&u.red[cjc][ig][0][lane << 2] = a0;
            *(float4*)&u.red[cjc][ig][1][lane << 2] = a1;
            *(float4*)&u.red[cjc][ig][2][lane << 2] = a2;
            *(float4*)&u.red[cjc][ig][3][lane << 2] = a3;
        }
        __syncthreads();
        if (cjc >= 4) {
            const int c = cjc - 4;
            float4* p0 = (float4*)&u.red[c][ig][0][lane << 2];
            float4* p1 = (float4*)&u.red[c][ig][1][lane << 2];
            float4* p2 = (float4*)&u.red[c][ig][2][lane << 2];
            float4* p3 = (float4*)&u.red[c][ig][3][lane << 2];
            float4 c0 = *p0, c1 = *p1, c2 = *p2, c3 = *p3;
            c0.x += a0.x; c0.y += a0.y; c0.z += a0.z; c0.w += a0.w;
            c1.x += a1.x; c1.y += a1.y; c1.z += a1.z; c1.w += a1.w;
            c2.x += a2.x; c2.y += a2.y; c2.z += a2.z; c2.w += a2.w;
            c3.x += a3.x; c3.y += a3.y; c3.z += a3.z; c3.w += a3.w;
            *p0 = c0; *p1 = c1; *p2 = c2; *p3 = c3;
        }
    }
    __syncthreads();

    // ---- Phase 4b: final 4-way sum + store (one warp per i-row) ----
    if (w < 8) {
        const int r  = w;
        const int gg = r >> 2;
        const int ir = r & 3;
        const float4 v0 = *(const float4*)&u.red[0][gg][ir][lane << 2];
        const float4 v1 = *(const float4*)&u.red[1][gg][ir][lane << 2];
        const float4 v2 = *(const float4*)&u.red[2][gg][ir][lane << 2];
        const float4 v3 = *(const float4*)&u.red[3][gg][ir][lane << 2];
        float4 o;
        o.x = (v0.x + v1.x) + (v2.x + v3.x);
        o.y = (v0.y + v1.y) + (v2.y + v3.y);
        o.z = (v0.z + v1.z) + (v2.z + v3.z);
        o.w = (v0.w + v1.w) + (v2.w + v3.w);
        *(float4*)&out[((size_t)b * LL + i0 + r) * DD + (lane << 2)] = o;
    }
}

// ---------------------------------------------------------------------------
extern "C" void kernel_launch(void* const* d_in, const int* in_sizes, int n_in,
                              void* d_out, int out_size)
{
    const float* inp = (const float*)d_in[0];
    const float* uw  = (const float*)d_in[1];
    const float* vw  = (const float*)d_in[2];
    const float* aw  = (const float*)d_in[3];

    float* out  = (float*)d_out;
    float* attn = out + BB * LL * DD;

    proj_kernel<<<BB * (LL / 32), 256>>>(inp, uw, vw);
    attn_kernel<<<BB * (LL / 8), 512>>>(inp, aw, out, attn);
}

// round 12
// speedup vs baseline: 1.3385x; 1.0856x over previous
#include <cuda_runtime.h>

#define BB 8
#define LL 512
#define DD 128

typedef unsigned long long ull;

// Scratch (allocation-free rule: __device__ globals)
__device__ float g_eq[BB * DD * LL];  // [b][d][l]  e^{2q}, l contiguous
__device__ float g_ek[BB * LL * DD];  // [b][l][d]  e^{2k}

// ---- packed f32x2 helpers (sm_100a) ----
__device__ __forceinline__ ull fma2(ull a, ull b, ull c) {
    ull d; asm("fma.rn.f32x2 %0, %1, %2, %3;" : "=l"(d) : "l"(a), "l"(b), "l"(c)); return d;
}
__device__ __forceinline__ ull mul2(ull a, ull b) {
    ull d; asm("mul.rn.f32x2 %0, %1, %2;" : "=l"(d) : "l"(a), "l"(b)); return d;
}
__device__ __forceinline__ ull rcp2(ull x) {   // rcp of both packed halves
    ull y;
    asm("{\n\t.reg .f32 lo, hi;\n\t"
        "mov.b64 {lo, hi}, %1;\n\t"
        "rcp.approx.f32 lo, lo;\n\t"
        "rcp.approx.f32 hi, hi;\n\t"
        "mov.b64 %0, {lo, hi};\n\t}"
        : "=l"(y) : "l"(x));
    return y;
}
__device__ __forceinline__ ull dup_f32(float v) {
    ull d; asm("mov.b64 %0, {%1, %1};" : "=l"(d) : "f"(v)); return d;
}

#define ONE2 0x3F8000003F800000ULL

// ---------------------------------------------------------------------------
// Kernel A: Eq = exp(2 * inp@u_w^T) stored transposed [b][d][l],
//           Ek = exp(2 * inp@v_w^T) row-major [b][l][d]
// ---------------------------------------------------------------------------
__global__ __launch_bounds__(256, 2) void proj_kernel(
    const float* __restrict__ inp,
    const float* __restrict__ uw,
    const float* __restrict__ vw)
{
    __shared__ float xS[32][32];
    __shared__ float wuS[128][33];
    __shared__ float wvS[128][33];

    const int b    = blockIdx.x >> 4;
    const int l0   = (blockIdx.x & 15) << 5;
    const int t    = threadIdx.x;
    const int lane = t & 31;
    const int warp = t >> 5;
    const int lrow = warp << 2;

    float qacc[4][4], kacc[4][4];
#pragma unroll
    for (int i = 0; i < 4; i++)
#pragma unroll
        for (int jj = 0; jj < 4; jj++) { qacc[i][jj] = 0.f; kacc[i][jj] = 0.f; }

    for (int kc = 0; kc < 4; kc++) {
        const int d0 = kc << 5;
        for (int idx = t; idx < 32 * 32; idx += 256) {
            int r = idx >> 5, c = idx & 31;
            xS[r][c] = inp[(b * LL + l0 + r) * DD + d0 + c];
        }
        for (int idx = t; idx < 128 * 32; idx += 256) {
            int r = idx >> 5, c = idx & 31;
            wuS[r][c] = uw[r * DD + d0 + c];
            wvS[r][c] = vw[r * DD + d0 + c];
        }
        __syncthreads();

#pragma unroll 8
        for (int d = 0; d < 32; d++) {
            const float x0 = xS[lrow + 0][d];
            const float x1 = xS[lrow + 1][d];
            const float x2 = xS[lrow + 2][d];
            const float x3 = xS[lrow + 3][d];
#pragma unroll
            for (int jj = 0; jj < 4; jj++) {
                const int e = lane + (jj << 5);
                const float wu = wuS[e][d];
                const float wv = wvS[e][d];
                qacc[0][jj] = fmaf(x0, wu, qacc[0][jj]);
                qacc[1][jj] = fmaf(x1, wu, qacc[1][jj]);
                qacc[2][jj] = fmaf(x2, wu, qacc[2][jj]);
                qacc[3][jj] = fmaf(x3, wu, qacc[3][jj]);
                kacc[0][jj] = fmaf(x0, wv, kacc[0][jj]);
                kacc[1][jj] = fmaf(x1, wv, kacc[1][jj]);
                kacc[2][jj] = fmaf(x2, wv, kacc[2][jj]);
                kacc[3][jj] = fmaf(x3, wv, kacc[3][jj]);
            }
        }
        __syncthreads();
    }

#pragma unroll
    for (int jj = 0; jj < 4; jj++) {
        const int e = lane + (jj << 5);
#pragma unroll
        for (int i = 0; i < 4; i++) {
            const int l = l0 + lrow + i;
            g_eq[((size_t)b * DD + e) * LL + l] = __expf(2.0f * qacc[i][jj]);
            g_ek[((size_t)b * LL + l) * DD + e] = __expf(2.0f * kacc[i][jj]);
        }
    }
}

// ---------------------------------------------------------------------------
// Kernel B: fused score + softmax + attn-write + out GEMM.
// Phase 2: packed f32x2 over j-pairs, ONE rcp per FOUR d's:
//   -(a1/x1+a2/x2+a3/x3+a4/x4) = num/den,
//   num = t1*p34 + t2*p12, den = p12*p34 (t = pair numerators, p = pair dens).
// Phase 4: packed f32x2 over d, weights as natural float2 pairs.
// ---------------------------------------------------------------------------
__global__ __launch_bounds__(512, 2) void attn_kernel(
    const float* __restrict__ inp,
    const float* __restrict__ aw,
    float* __restrict__ out,
    float* __restrict__ attn)
{
    union U {
        struct {                        // alive through phase 3
            ulonglong2 ekD[8][64];      // Ek dup'd: [ii][d/2] = (dup d, dup d+1)
            ulonglong2 naD[64];         // -a dup'd pairs
            float scp1[8][512];         // h=1 partial scores
        } p2;
        float red[4][2][4][DD];         // phase 4 partials (overlays p2)
    };
    __shared__ __align__(16) U u;
    __shared__ float sc[8][512];        // h=0 partials -> attn weights

    const int b    = blockIdx.x >> 6;
    const int i0   = (blockIdx.x & 63) << 3;
    const int t    = threadIdx.x;
    const int lane = t & 31;
    const int w    = t >> 5;

    // Stage Ek (duplicated pairs) and -a (duplicated pairs)
    {
        const float* __restrict__ ekbase = g_ek + ((size_t)b * LL + i0) * DD;
        for (int idx = t; idx < 8 * 64; idx += 512) {
            const int ii = idx >> 6, dp = idx & 63;
            const float2 kv = *(const float2*)(ekbase + ii * DD + (dp << 1));
            u.p2.ekD[ii][dp] = make_ulonglong2(dup_f32(kv.x), dup_f32(kv.y));
        }
    }
    if (t < 64) {
        const float2 a2 = ((const float2*)aw)[t];
        u.p2.naD[t] = make_ulonglong2(dup_f32(-a2.x), dup_f32(-a2.y));
    }
    __syncthreads();

    // ---- Phase 2: partial -sum_d a_d/(Eq*Ek+1) over this warp's d-half ----
    const int h     = w >> 3;            // d-half
    const int jc    = w & 7;             // 64-j tile
    const int jb    = jc << 6;
    const int dbase = h << 6;

    ull acc2[8];
#pragma unroll
    for (int ii = 0; ii < 8; ii++) acc2[ii] = 0ULL;

    // float2 view of g_eq: row d has LL/2 float2s; lane owns pair (jb+2*lane)
    const float2* __restrict__ eqp2 =
        (const float2*)g_eq + (size_t)b * DD * (LL >> 1) + (jb >> 1) + lane;

#pragma unroll 2
    for (int p = 0; p < 16; p++) {
        const int d0 = dbase + (p << 2);
        const ull eqA = *(const ull*)(eqp2 + (size_t)(d0 + 0) * (LL >> 1));
        const ull eqB = *(const ull*)(eqp2 + (size_t)(d0 + 1) * (LL >> 1));
        const ull eqC = *(const ull*)(eqp2 + (size_t)(d0 + 2) * (LL >> 1));
        const ull eqD = *(const ull*)(eqp2 + (size_t)(d0 + 3) * (LL >> 1));
        const ulonglong2 naAB = u.p2.naD[(d0 >> 1) + 0];   // LDS.128 broadcast
        const ulonglong2 naCD = u.p2.naD[(d0 >> 1) + 1];
#pragma unroll
        for (int ii = 0; ii < 8; ii++) {
            const ulonglong2 ekAB = u.p2.ekD[ii][(d0 >> 1) + 0];  // LDS.128
            const ulonglong2 ekCD = u.p2.ekD[ii][(d0 >> 1) + 1];
            const ull x1 = fma2(eqA, ekAB.x, ONE2);
            const ull x2 = fma2(eqB, ekAB.y, ONE2);
            const ull x3 = fma2(eqC, ekCD.x, ONE2);
            const ull x4 = fma2(eqD, ekCD.y, ONE2);
            // pair numerators (carry -a) and pair denominators
            ull t1 = mul2(naAB.x, x2); t1 = fma2(naAB.y, x1, t1);
            ull t2 = mul2(naCD.x, x4); t2 = fma2(naCD.y, x3, t2);
            const ull p12 = mul2(x1, x2);
            const ull p34 = mul2(x3, x4);
            // quad combine: one rcp per 4 d's
            ull num = mul2(t1, p34); num = fma2(t2, p12, num);
            const ull den = mul2(p12, p34);
            const ull r   = rcp2(den);
            acc2[ii] = fma2(num, r, acc2[ii]);
        }
    }
    {
        float (* __restrict__ dst)[512] = (h == 0) ? sc : u.p2.scp1;
        const int j = jb + (lane << 1);
#pragma unroll
        for (int ii = 0; ii < 8; ii++)
            *(ull*)&dst[ii][j] = acc2[ii];    // STS.64, (j, j+1) adjacent
    }
    __syncthreads();

    // ---- Phase 3: softmax over j (score = 2*(sc + scp1) + const) ----
    if (w < 8) {
        const int r = w;
        float v[16];
        float mx = -1e30f;
#pragma unroll
        for (int q = 0; q < 16; q++) {
            const int jj = lane + (q << 5);
            v[q] = 2.0f * (sc[r][jj] + u.p2.scp1[r][jj]);
            mx = fmaxf(mx, v[q]);
        }
#pragma unroll
        for (int o = 16; o > 0; o >>= 1) mx = fmaxf(mx, __shfl_xor_sync(0xffffffffu, mx, o));
        float s = 0.f;
#pragma unroll
        for (int q = 0; q < 16; q++) { v[q] = __expf(v[q] - mx); s += v[q]; }
#pragma unroll
        for (int o = 16; o > 0; o >>= 1) s += __shfl_xor_sync(0xffffffffu, s, o);
        const float inv = 1.0f / s;
        float* arow = attn + ((size_t)b * LL + i0 + r) * LL;
#pragma unroll
        for (int q = 0; q < 16; q++) {
            const int jj = lane + (q << 5);
            const float av = v[q] * inv;
            sc[r][jj] = av;       // reuse for phase 4
            arow[jj]  = av;       // coalesced attn output
        }
    }
    __syncthreads();   // scp1/staging dead beyond this point -> red may overlay

    // ---- Phase 4a: packed-d partial out over 64 j's for 4 i-rows per warp --
    const int ig = w >> 3;   // i-group: rows ig*4 .. ig*4+3
    const int cjc = w & 7;   // j-chunk: [cjc*64, cjc*64+64)
    {
        ull accA[4], accB[4];  // per i-row: (d0,d1) and (d2,d3) of lane's 4 d's
#pragma unroll
        for (int i = 0; i < 4; i++) { accA[i] = 0ULL; accB[i] = 0ULL; }

        const ull* __restrict__ xin =
            (const ull*)(inp + ((size_t)b * LL + (cjc << 6)) * DD) + (lane << 1);
        const float2* __restrict__ s0 = (const float2*)&sc[(ig << 2) + 0][cjc << 6];
        const float2* __restrict__ s1 = (const float2*)&sc[(ig << 2) + 1][cjc << 6];
        const float2* __restrict__ s2 = (const float2*)&sc[(ig << 2) + 2][cjc << 6];
        const float2* __restrict__ s3 = (const float2*)&sc[(ig << 2) + 3][cjc << 6];
#pragma unroll 4
        for (int jj = 0; jj < 32; jj++) {
            const float2 w0 = s0[jj];               // (w_{2jj}, w_{2jj+1})
            const float2 w1 = s1[jj];
            const float2 w2 = s2[jj];
            const float2 w3 = s3[jj];
            const ull xaA = xin[(2 * jj + 0) * (DD / 2)];      // LDG.128 halves
            const ull xaB = xin[(2 * jj + 0) * (DD / 2) + 1];
            const ull xbA = xin[(2 * jj + 1) * (DD / 2)];
            const ull xbB = xin[(2 * jj + 1) * (DD / 2) + 1];
            {
                const ull dx = dup_f32(w0.x), dy = dup_f32(w0.y);
                accA[0] = fma2(dx, xaA, accA[0]); accB[0] = fma2(dx, xaB, accB[0]);
                accA[0] = fma2(dy, xbA, accA[0]); accB[0] = fma2(dy, xbB, accB[0]);
            }
            {
                const ull dx = dup_f32(w1.x), dy = dup_f32(w1.y);
                accA[1] = fma2(dx, xaA, accA[1]); accB[1] = fma2(dx, xaB, accB[1]);
                accA[1] = fma2(dy, xbA, accA[1]); accB[1] = fma2(dy, xbB, accB[1]);
            }
            {
                const ull dx = dup_f32(w2.x), dy = dup_f32(w2.y);
                accA[2] = fma2(dx, xaA, accA[2]); accB[2] = fma2(dx, xaB, accB[2]);
                accA[2] = fma2(dy, xbA, accA[2]); accB[2] = fma2(dy, xbB, accB[2]);
            }
            {
                const ull dx = dup_f32(w3.x), dy = dup_f32(w3.y);
                accA[3] = fma2(dx, xaA, accA[3]); accB[3] = fma2(dx, xaB, accB[3]);
                accA[3] = fma2(dy, xbA, accA[3]); accB[3] = fma2(dy, xbB, accB[3]);
            }
        }
        if (cjc < 4) {
#pragma unroll
            for (int i = 0; i < 4; i++) {
                *(ull*)&u.red[cjc][ig][i][lane << 2]       = accA[i];
                *(ull*)&u.red[cjc][ig][i][(lane << 2) + 2] = accB[i];
            }
        }
        __syncthreads();
        if (cjc >= 4) {
            const int c = cjc - 4;
#pragma unroll
            for (int i = 0; i < 4; i++) {
                ull* pA = (ull*)&u.red[c][ig][i][lane << 2];
                ull* pB = (ull*)&u.red[c][ig][i][(lane << 2) + 2];
                *pA = fma2(accA[i], ONE2, *pA);   // acc*1 + prev
                *pB = fma2(accB[i], ONE2, *pB);
            }
        }
    }
    __syncthreads();

    // ---- Phase 4b: final 4-way sum + store (one warp per i-row) ----
    if (w < 8) {
        const int r  = w;
        const int gg = r >> 2;
        const int ir = r & 3;
        const float4 v0 = *(const float4*)&u.red[0][gg][ir][lane << 2];
        const float4 v1 = *(const float4*)&u.red[1][gg][ir][lane << 2];
        const float4 v2 = *(const float4*)&u.red[2][gg][ir][lane << 2];
        const float4 v3 = *(const float4*)&u.red[3][gg][ir][lane << 2];
        float4 o;
        o.x = (v0.x + v1.x) + (v2.x + v3.x);
        o.y = (v0.y + v1.y) + (v2.y + v3.y);
        o.z = (v0.z + v1.z) + (v2.z + v3.z);
        o.w = (v0.w + v1.w) + (v2.w + v3.w);
        *(float4*)&out[((size_t)b * LL + i0 + r) * DD + (lane << 2)] = o;
    }
}

// ---------------------------------------------------------------------------
extern "C" void kernel_launch(void* const* d_in, const int* in_sizes, int n_in,
                              void* d_out, int out_size)
{
    const float* inp = (const float*)d_in[0];
    const float* uw  = (const float*)d_in[1];
    const float* vw  = (const float*)d_in[2];
    const float* aw  = (const float*)d_in[3];

    float* out  = (float*)d_out;
    float* attn = out + BB * LL * DD;

    proj_kernel<<<BB * (LL / 32), 256>>>(inp, uw, vw);
    attn_kernel<<<BB * (LL / 8), 512>>>(inp, aw, out, attn);
}